// round 12
// baseline (speedup 1.0000x reference)
#include <cuda_runtime.h>
#include <cuda_bf16.h>
#include <cstdint>

// ---------------- problem constants ----------------
#define BB   2
#define CC   128
#define HH   128
#define WW   128
#define HL   64
#define WL   64
#define QQ   65536
#define BQ   (BB*QQ)          // 131072
#define RTOT (4*BQ)           // 524288
#define ROWS 128              // rows per CTA (MMA M)
#define NCTA (RTOT/ROWS)      // 4096

// ---------------- smem layout (bytes) ----------------
// A buffers: [128 r][32 segs of 8 bf16], unit = r*32 + (seg ^ (r&7)), 16B units
#define A_HI 0                // 65536
#define A_LO 65536            // 65536
// B staging (double-buffered k-quarters): [256 n][8 segs], unit = n*8 + (sg ^ (n&7))
#define BST0 131072           // 32768
#define BST1 163840           // 32768
#define BIAS 196608           // 256 f32
#define W4S  197632           // [3][256] f32
#define WT   200704           // wtail [6][256] f32
#define XT   206848           // xtail [6][128] f32 (reused for head partials)
#define AREA 209920           // 128 f32
#define SMEMB 210432
#define VSTR 258              // fp32 v-buffer row stride (overlays A_HI/A_LO/BST0 at l==3)

// ---------------- device scratch (static; no allocation) ----------------
__device__ float g_featT[(size_t)BB*HH*WW*CC];       // NHWC feat fp32
__device__ float g_lrT  [(size_t)BB*HL*WL*CC];       // NHWC lr fp32
__device__ float g_predArea[(size_t)RTOT*4];         // pred.xyz + area
// weights pre-transposed to [layer][n 0..255][k 0..255] bf16 (hi and residual-lo)
__device__ __nv_bfloat16 g_Bh[4*65536];
__device__ __nv_bfloat16 g_Bl[4*65536];

__device__ __forceinline__ uint32_t smem_u32(const void* p) {
    uint32_t a;
    asm("{ .reg .u64 t; cvta.to.shared.u64 t, %1; cvt.u32.u64 %0, t; }" : "=r"(a) : "l"(p));
    return a;
}
__device__ __forceinline__ void ldsm4(uint32_t& q0, uint32_t& q1, uint32_t& q2, uint32_t& q3,
                                      uint32_t addr) {
    asm volatile("ldmatrix.sync.aligned.m8n8.x4.shared.b16 {%0,%1,%2,%3}, [%4];"
                 : "=r"(q0), "=r"(q1), "=r"(q2), "=r"(q3) : "r"(addr));
}
__device__ __forceinline__ void mma_bf16(float* d, const uint32_t* a, const uint32_t* b) {
    asm volatile("mma.sync.aligned.m16n8k16.row.col.f32.bf16.bf16.f32 "
                 "{%0,%1,%2,%3}, {%4,%5,%6,%7}, {%8,%9}, {%0,%1,%2,%3};"
                 : "+f"(d[0]), "+f"(d[1]), "+f"(d[2]), "+f"(d[3])
                 : "r"(a[0]), "r"(a[1]), "r"(a[2]), "r"(a[3]), "r"(b[0]), "r"(b[1]));
}
__device__ __forceinline__ uint32_t pk(__nv_bfloat16 a, __nv_bfloat16 b) {
    return (uint32_t)__bfloat16_as_ushort(a) | ((uint32_t)__bfloat16_as_ushort(b) << 16);
}
__device__ __forceinline__ void cp16(uint32_t dst, const void* src) {
    asm volatile("cp.async.cg.shared.global [%0], [%1], 16;" :: "r"(dst), "l"(src));
}
#define CP_COMMIT() asm volatile("cp.async.commit_group;" ::: "memory")
#define CP_WAIT0()  asm volatile("cp.async.wait_group 0;" ::: "memory")

// ---------------- kernel 1: NCHW -> NHWC tiled transpose ----------------
__global__ void transpose_kernel(const float* __restrict__ src, int Hh, int Ww, int mode)
{
    __shared__ float tile[32][33];
    float* dst = mode ? g_lrT : g_featT;
    const int x0 = blockIdx.x * 32;
    const int c0 = blockIdx.y * 32;
    const int bz = blockIdx.z;
    const int b  = bz / Hh, y = bz % Hh;
    const int txi = threadIdx.x, tyi = threadIdx.y;   // 32 x 8
#pragma unroll
    for (int j = 0; j < 4; j++) {
        int c = c0 + tyi + j * 8;
        tile[tyi + j * 8][txi] = src[(((size_t)b * CC + c) * Hh + y) * Ww + x0 + txi];
    }
    __syncthreads();
#pragma unroll
    for (int j = 0; j < 4; j++) {
        int x = x0 + tyi + j * 8;
        dst[(((size_t)b * Hh + y) * Ww + x) * CC + c0 + txi] = tile[txi][tyi + j * 8];
    }
}

// ---------------- kernel 2: weight prep (transpose + bf16 split) ----------------
__global__ void prep_weights(const float* __restrict__ W0, const float* __restrict__ W1,
                             const float* __restrict__ W2, const float* __restrict__ W3)
{
    int id = blockIdx.x * 256 + threadIdx.x;      // 4*256*256
    int l  = id >> 16;
    int n  = (id >> 8) & 255;
    int k  = id & 255;
    const float* Wl = (l == 0) ? W0 : (l == 1) ? W1 : (l == 2) ? W2 : W3;
    // layer0 k remap: k<128 -> feat chan k ; k>=128 -> lr chan => W0 row 130+(k-128)
    int ksrc = (l == 0 && k >= 128) ? (130 + (k - 128)) : k;
    float w = Wl[ksrc * 256 + n];
    __nv_bfloat16 h  = __float2bfloat16(w);
    __nv_bfloat16 lo = __float2bfloat16(w - __bfloat162float(h));
    g_Bh[id] = h;
    g_Bl[id] = lo;
}

// async-stage one k-quarter (64 k = 8 segs) of one layer's B into a 32KB buffer
__device__ __forceinline__ void prefetchB(const __nv_bfloat16* src, uint32_t dbase, int q, int t)
{
    const uint4* s = (const uint4*)src;
#pragma unroll
    for (int i = 0; i < 8; i++) {
        int idx = i * 256 + t;                    // 0..2047
        int n = idx >> 3, j = idx & 7;
        uint32_t dst = dbase + (uint32_t)((n * 8 + (j ^ (n & 7))) * 16);
        cp16(dst, s + n * 32 + q * 8 + j);
    }
}

// split fp32 pair -> bf16 hi/lo, store to A buffers (swizzled)
__device__ __forceinline__ void store_pair(char* smem, int r0, int c, float v0, float v1)
{
    __nv_bfloat16 h0 = __float2bfloat16(v0), h1 = __float2bfloat16(v1);
    __nv_bfloat16 g0 = __float2bfloat16(v0 - __bfloat162float(h0));
    __nv_bfloat16 g1 = __float2bfloat16(v1 - __bfloat162float(h1));
    int unit = r0 * 32 + ((c >> 3) ^ (r0 & 7));
    int boff = unit * 16 + (c & 7) * 2;
    *(uint32_t*)(smem + A_HI + boff) = pk(h0, h1);
    *(uint32_t*)(smem + A_LO + boff) = pk(g0, g1);
}

// ---------------- kernel 3: fused gather + HMMA MLP, cp.async pipelined ------------
__global__ void __launch_bounds__(256, 1) mlp_mma(
    const float* __restrict__ coord, const float* __restrict__ cell,
    const float* __restrict__ W0, const float* __restrict__ b0,
    const float* __restrict__ b1, const float* __restrict__ b2,
    const float* __restrict__ b3,
    const float* __restrict__ W4, const float* __restrict__ b4)
{
    extern __shared__ char smem[];
    float* smf = (float*)smem;
    const int t = threadIdx.x;
    const int lane = t & 31, w = t >> 5;
    const uint32_t sb = smem_u32(smem);

    // kick off layer-0 stage-0 B prefetch immediately (hidden under gathers)
    prefetchB(g_Bh, sb + BST0, 0, t);
    CP_COMMIT();

    // ---- phase 0: geometry + gathers (2 threads per row) ----
    {
        const int r = t >> 1, half = t & 1;
        const int rg  = blockIdx.x * ROWS + r;
        const int s   = rg >> 17;
        const int rem = rg & (BQ - 1);
        const int b   = rem >> 16;
        const float cy = coord[2 * rem + 0];
        const float cx = coord[2 * rem + 1];
        const float vx = (s & 2) ? 1.f : -1.f;
        const float vy = (s & 1) ? 1.f : -1.f;
        const float r128 = 1.f / 128.f;
        float cy_ = fminf(fmaxf(cy + (vx * r128 + 1e-6f), -1.f + 1e-6f), 1.f - 1e-6f);
        float cx_ = fminf(fmaxf(cx + (vy * r128 + 1e-6f), -1.f + 1e-6f), 1.f - 1e-6f);
        int iy  = min(max((int)floorf(((cy_ + 1.f) * 128.f - 1.f) * 0.5f + 0.5f), 0), 127);
        int ix  = min(max((int)floorf(((cx_ + 1.f) * 128.f - 1.f) * 0.5f + 0.5f), 0), 127);
        int liy = min(max((int)floorf(((cy_ + 1.f) * 64.f - 1.f) * 0.5f + 0.5f), 0), 63);
        int lix = min(max((int)floorf(((cx_ + 1.f) * 64.f - 1.f) * 0.5f + 0.5f), 0), 63);
        if (half == 0) {
            float qy = -1.f + (2.f * (float)iy + 1.f) * r128;
            float qx = -1.f + (2.f * (float)ix + 1.f) * r128;
            float rel_y = (cy - qy) * 128.f;
            float rel_x = (cx - qx) * 128.f;
            smf[XT / 4 + 0 * 128 + r] = rel_y;
            smf[XT / 4 + 1 * 128 + r] = rel_x;
            smf[XT / 4 + 2 * 128 + r] = -1.f + (2.f * (float)liy + 1.f) * (1.f / 64.f);
            smf[XT / 4 + 3 * 128 + r] = -1.f + (2.f * (float)lix + 1.f) * (1.f / 64.f);
            smf[XT / 4 + 4 * 128 + r] = cell[2 * rem + 0] * 128.f;
            smf[XT / 4 + 5 * 128 + r] = cell[2 * rem + 1] * 128.f;
            smf[AREA / 4 + r] = fabsf(rel_y * rel_x) + 1e-9f;
        }
        const float4* fb = half
            ? (const float4*)(g_lrT   + (size_t)(((b * HL + liy) * WL + lix)) * CC)
            : (const float4*)(g_featT + (size_t)(((b * HH + iy) * WW + ix)) * CC);
        const int r7r = r & 7;
#pragma unroll 8
        for (int i = 0; i < 32; i++) {
            float4 u = fb[i];
            int c = half * 128 + i * 4;
            __nv_bfloat16 h0 = __float2bfloat16(u.x), h1 = __float2bfloat16(u.y);
            __nv_bfloat16 h2 = __float2bfloat16(u.z), h3 = __float2bfloat16(u.w);
            __nv_bfloat16 l0 = __float2bfloat16(u.x - __bfloat162float(h0));
            __nv_bfloat16 l1 = __float2bfloat16(u.y - __bfloat162float(h1));
            __nv_bfloat16 l2 = __float2bfloat16(u.z - __bfloat162float(h2));
            __nv_bfloat16 l3 = __float2bfloat16(u.w - __bfloat162float(h3));
            int unit = r * 32 + ((c >> 3) ^ r7r);
            int boff = unit * 16 + (c & 7) * 2;
            *(uint2*)(smem + A_HI + boff) = make_uint2(pk(h0, h1), pk(h2, h3));
            *(uint2*)(smem + A_LO + boff) = make_uint2(pk(l0, l1), pk(l2, l3));
        }
        // wtail: W0 rows {128,129,258,259,260,261}
        {
            const int tailrow[6] = {128, 129, 258, 259, 260, 261};
            for (int idx = t; idx < 1536; idx += 256) {
                int jj = idx >> 8, c = idx & 255;
                smf[WT / 4 + jj * 256 + c] = W0[tailrow[jj] * 256 + c];
            }
            for (int idx = t; idx < 768; idx += 256)
                smf[W4S / 4 + idx] = W4[(idx & 255) * 3 + (idx >> 8)];
        }
    }

    // ---- ldmatrix lane geometry ----
    const int laneAr = lane & 15, sa = lane >> 4, la7 = lane & 7;
    const int nb0 = w * 32 + ((lane >> 4) << 3) + (lane & 7);
    const int sbB = (lane >> 3) & 1;
    const int rq = lane >> 2, cq = (lane & 3) * 2;

    float acc[8][16];

    for (int l = 0; l < 4; l++) {
        __syncthreads();          // prev epilogue done (BIAS/A safe to rewrite)
        {
            const float* bg = (l == 0) ? b0 : (l == 1) ? b1 : (l == 2) ? b2 : b3;
            smf[BIAS / 4 + t] = bg[t];
        }
#pragma unroll
        for (int mt = 0; mt < 8; mt++)
#pragma unroll
            for (int q = 0; q < 16; q++) acc[mt][q] = 0.f;

        // 8 stages: s = 2*q + sel, sel 0 = W-hi (A_HI + A_LO terms), 1 = W-lo (A_HI term)
#pragma unroll 1
        for (int s = 0; s < 8; s++) {
            CP_WAIT0();
            __syncthreads();              // stage s data visible to all; prev MMA done
            if (s < 7) {                  // prefetch next stage into other buffer
                const __nv_bfloat16* nsrc = (((s + 1) & 1) ? g_Bl : g_Bh) + ((size_t)l << 16);
                prefetchB(nsrc, sb + (((s + 1) & 1) ? BST1 : BST0), (s + 1) >> 1, t);
                CP_COMMIT();
            }
            const uint32_t Bb = sb + ((s & 1) ? BST1 : BST0);
            const int q = s >> 1;
            const bool hiStage = ((s & 1) == 0);
#pragma unroll
            for (int ks = 0; ks < 4; ks++) {
                uint32_t bq[4][2];
                {
                    int seg = ks * 2 + sbB;
                    int n0 = nb0, n1 = nb0 + 16;
                    uint32_t ad0 = Bb + (uint32_t)((n0 * 8 + (seg ^ (n0 & 7))) * 16);
                    uint32_t ad1 = Bb + (uint32_t)((n1 * 8 + (seg ^ (n1 & 7))) * 16);
                    ldsm4(bq[0][0], bq[0][1], bq[1][0], bq[1][1], ad0);
                    ldsm4(bq[2][0], bq[2][1], bq[3][0], bq[3][1], ad1);
                }
                int segA = (q * 8 + ks * 2 + sa) ^ la7;
#pragma unroll
                for (int mt = 0; mt < 8; mt++) {
                    int rowA = mt * 16 + laneAr;
                    uint32_t aq[4];
                    ldsm4(aq[0], aq[1], aq[2], aq[3],
                          sb + A_HI + (uint32_t)((rowA * 32 + segA) * 16));
#pragma unroll
                    for (int j = 0; j < 4; j++) mma_bf16(acc[mt] + 4 * j, aq, bq[j]);
                    if (hiStage) {        // A_LO x W_hi correction term
                        ldsm4(aq[0], aq[1], aq[2], aq[3],
                              sb + A_LO + (uint32_t)((rowA * 32 + segA) * 16));
#pragma unroll
                        for (int j = 0; j < 4; j++) mma_bf16(acc[mt] + 4 * j, aq, bq[j]);
                    }
                }
            }
        }
        if (l < 3) {                      // prefetch next layer stage 0 (under epilogue)
            prefetchB(g_Bh + ((size_t)(l + 1) << 16), sb + BST0, 0, t);
            CP_COMMIT();
        }
        __syncthreads();                  // all MMA done; safe to overwrite A / v-buffer

        // ---- epilogue ----
        float wtc[6][8];
        if (l == 0) {
#pragma unroll
            for (int jj = 0; jj < 6; jj++)
#pragma unroll
                for (int j = 0; j < 4; j++) {
                    int c = w * 32 + j * 8 + cq;
                    wtc[jj][2 * j]     = smf[WT / 4 + jj * 256 + c];
                    wtc[jj][2 * j + 1] = smf[WT / 4 + jj * 256 + c + 1];
                }
        }
#pragma unroll
        for (int mt = 0; mt < 8; mt++) {
            int r0 = mt * 16 + rq;
            float xtr[6], xtr8[6];
            if (l == 0) {
#pragma unroll
                for (int jj = 0; jj < 6; jj++) {
                    xtr[jj]  = smf[XT / 4 + jj * 128 + r0];
                    xtr8[jj] = smf[XT / 4 + jj * 128 + r0 + 8];
                }
            }
#pragma unroll
            for (int j = 0; j < 4; j++) {
                int c = w * 32 + j * 8 + cq;
                float bs0 = smf[BIAS / 4 + c], bs1 = smf[BIAS / 4 + c + 1];
                float v0 = acc[mt][4 * j + 0] + bs0;
                float v1 = acc[mt][4 * j + 1] + bs1;
                float v2 = acc[mt][4 * j + 2] + bs0;
                float v3 = acc[mt][4 * j + 3] + bs1;
                if (l == 0) {
#pragma unroll
                    for (int jj = 0; jj < 6; jj++) {
                        v0 = fmaf(xtr[jj],  wtc[jj][2 * j],     v0);
                        v1 = fmaf(xtr[jj],  wtc[jj][2 * j + 1], v1);
                        v2 = fmaf(xtr8[jj], wtc[jj][2 * j],     v2);
                        v3 = fmaf(xtr8[jj], wtc[jj][2 * j + 1], v3);
                    }
                }
                v0 = fmaxf(v0, 0.f); v1 = fmaxf(v1, 0.f);
                v2 = fmaxf(v2, 0.f); v3 = fmaxf(v3, 0.f);
                if (l < 3) {
                    store_pair(smem, r0,     c, v0, v1);
                    store_pair(smem, r0 + 8, c, v2, v3);
                } else {
                    *(float2*)(smf + r0 * VSTR + c)       = make_float2(v0, v1);
                    *(float2*)(smf + (r0 + 8) * VSTR + c) = make_float2(v2, v3);
                }
            }
        }
    }

    // ---- head: out = v @ W4 + b4 ----
    __syncthreads();
    {
        const int hr = t >> 1, hh = t & 1;
        float a0 = 0.f, a1 = 0.f, a2 = 0.f;
        const float* vrow = smf + hr * VSTR + hh * 128;
        const float* w4p  = smf + W4S / 4 + hh * 128;
#pragma unroll 8
        for (int c2 = 0; c2 < 128; c2++) {
            float x = vrow[c2];
            a0 = fmaf(x, w4p[0 * 256 + c2], a0);
            a1 = fmaf(x, w4p[1 * 256 + c2], a1);
            a2 = fmaf(x, w4p[2 * 256 + c2], a2);
        }
        __syncthreads();          // v-buffer reads done before XT overwrite
        smf[XT / 4 + t * 3 + 0] = a0;
        smf[XT / 4 + t * 3 + 1] = a1;
        smf[XT / 4 + t * 3 + 2] = a2;
    }
    __syncthreads();
    if (t < 128) {
        const size_t rgi = (size_t)(blockIdx.x * ROWS + t) * 4;
        g_predArea[rgi + 0] = smf[XT / 4 + (2 * t) * 3 + 0] + smf[XT / 4 + (2 * t + 1) * 3 + 0] + b4[0];
        g_predArea[rgi + 1] = smf[XT / 4 + (2 * t) * 3 + 1] + smf[XT / 4 + (2 * t + 1) * 3 + 1] + b4[1];
        g_predArea[rgi + 2] = smf[XT / 4 + (2 * t) * 3 + 2] + smf[XT / 4 + (2 * t + 1) * 3 + 2] + b4[2];
        g_predArea[rgi + 3] = smf[AREA / 4 + t];
    }
}

// ---------------- kernel 4: local-ensemble combine (diagonal area swap) -------------
__global__ void combine_kernel(float* __restrict__ out)
{
    const int idx = blockIdx.x * 256 + threadIdx.x;     // b*Q + q
    const float4 p0 = *(const float4*)(g_predArea + ((size_t)(0 * BQ + idx)) * 4);
    const float4 p1 = *(const float4*)(g_predArea + ((size_t)(1 * BQ + idx)) * 4);
    const float4 p2 = *(const float4*)(g_predArea + ((size_t)(2 * BQ + idx)) * 4);
    const float4 p3 = *(const float4*)(g_predArea + ((size_t)(3 * BQ + idx)) * 4);
    const float tot = p0.w + p1.w + p2.w + p3.w;
    const float w0 = p3.w / tot, w1 = p2.w / tot, w2 = p1.w / tot, w3 = p0.w / tot;
    out[idx * 3 + 0] = p0.x * w0 + p1.x * w1 + p2.x * w2 + p3.x * w3;
    out[idx * 3 + 1] = p0.y * w0 + p1.y * w1 + p2.y * w2 + p3.y * w3;
    out[idx * 3 + 2] = p0.z * w0 + p1.z * w1 + p2.z * w2 + p3.z * w3;
}

// ---------------- launch ----------------
extern "C" void kernel_launch(void* const* d_in, const int* in_sizes, int n_in,
                              void* d_out, int out_size)
{
    const float* feat  = (const float*)d_in[0];
    const float* lrft  = (const float*)d_in[1];
    const float* coord = (const float*)d_in[2];
    const float* cell  = (const float*)d_in[3];
    const float* W0 = (const float*)d_in[4];   const float* b0 = (const float*)d_in[5];
    const float* W1 = (const float*)d_in[6];   const float* b1 = (const float*)d_in[7];
    const float* W2 = (const float*)d_in[8];   const float* b2 = (const float*)d_in[9];
    const float* W3 = (const float*)d_in[10];  const float* b3 = (const float*)d_in[11];
    const float* W4 = (const float*)d_in[12];  const float* b4 = (const float*)d_in[13];
    float* out = (float*)d_out;

    cudaFuncSetAttribute((const void*)mlp_mma,
                         cudaFuncAttributeMaxDynamicSharedMemorySize, SMEMB);

    dim3 blkT(32, 8);
    transpose_kernel<<<dim3(WW / 32, CC / 32, BB * HH), blkT>>>(feat, HH, WW, 0);
    transpose_kernel<<<dim3(WL / 32, CC / 32, BB * HL), blkT>>>(lrft, HL, WL, 1);
    prep_weights<<<1024, 256>>>(W0, W1, W2, W3);

    mlp_mma<<<NCTA, 256, SMEMB>>>(coord, cell, W0, b0, b1, b2, b3, W4, b4);

    combine_kernel<<<BQ / 256, 256>>>(out);
}

// round 14
// speedup vs baseline: 1.0634x; 1.0634x over previous
#include <cuda_runtime.h>
#include <cuda_bf16.h>
#include <cstdint>

// ---------------- problem constants ----------------
#define BB   2
#define CC   128
#define HH   128
#define WW   128
#define HL   64
#define WL   64
#define QQ   65536
#define BQ   (BB*QQ)          // 131072
#define RTOT (4*BQ)           // 524288
#define ROWS 64               // rows per CTA (MMA M)
#define NCTA (RTOT/ROWS)      // 8192

// ---------------- smem layout (bytes) ----------------
// A buffers: [64 r][32 segs of 8 bf16], unit = r*32 + (seg ^ (r&7)), 16B units
#define A_HI 0                // 32768
#define A_LO 32768            // 32768
// B staging (double-buffered k-eighths): [256 n][4 segs], unit = n*4 + (sg ^ ((n>>1)&3))
#define BST0 65536            // 16384
#define BST1 81920            // 16384
#define BIAS 98304            // 256 f32
#define W4S  99328            // [3][256] f32
#define WT   102400           // wtail [6][256] f32
#define XT   108544           // xtail [6][64] f32 (reused for head partials)
#define AREA 110080           // 64 f32
#define SMEMB 110336
#define VSTR 258              // fp32 v-buffer row stride (overlays A_HI/A_LO/BST0 at l==3)

// ---------------- device scratch (static; no allocation) ----------------
__device__ float g_featT[(size_t)BB*HH*WW*CC];       // NHWC feat fp32
__device__ float g_lrT  [(size_t)BB*HL*WL*CC];       // NHWC lr fp32
__device__ float g_predArea[(size_t)RTOT*4];         // pred.xyz + area
// weights pre-transposed to [layer][n 0..255][k 0..255] bf16 (hi and residual-lo)
__device__ __nv_bfloat16 g_Bh[4*65536];
__device__ __nv_bfloat16 g_Bl[4*65536];

__device__ __forceinline__ uint32_t smem_u32(const void* p) {
    uint32_t a;
    asm("{ .reg .u64 t; cvta.to.shared.u64 t, %1; cvt.u32.u64 %0, t; }" : "=r"(a) : "l"(p));
    return a;
}
__device__ __forceinline__ void ldsm4(uint32_t& q0, uint32_t& q1, uint32_t& q2, uint32_t& q3,
                                      uint32_t addr) {
    asm volatile("ldmatrix.sync.aligned.m8n8.x4.shared.b16 {%0,%1,%2,%3}, [%4];"
                 : "=r"(q0), "=r"(q1), "=r"(q2), "=r"(q3) : "r"(addr));
}
__device__ __forceinline__ void mma_bf16(float* d, const uint32_t* a, const uint32_t* b) {
    asm volatile("mma.sync.aligned.m16n8k16.row.col.f32.bf16.bf16.f32 "
                 "{%0,%1,%2,%3}, {%4,%5,%6,%7}, {%8,%9}, {%0,%1,%2,%3};"
                 : "+f"(d[0]), "+f"(d[1]), "+f"(d[2]), "+f"(d[3])
                 : "r"(a[0]), "r"(a[1]), "r"(a[2]), "r"(a[3]), "r"(b[0]), "r"(b[1]));
}
__device__ __forceinline__ uint32_t pk(__nv_bfloat16 a, __nv_bfloat16 b) {
    return (uint32_t)__bfloat16_as_ushort(a) | ((uint32_t)__bfloat16_as_ushort(b) << 16);
}
__device__ __forceinline__ void cp16(uint32_t dst, const void* src) {
    asm volatile("cp.async.cg.shared.global [%0], [%1], 16;" :: "r"(dst), "l"(src));
}
#define CP_COMMIT() asm volatile("cp.async.commit_group;" ::: "memory")
#define CP_WAIT0()  asm volatile("cp.async.wait_group 0;" ::: "memory")

// ---------------- kernel 1: NCHW -> NHWC tiled transpose ----------------
__global__ void transpose_kernel(const float* __restrict__ src, int Hh, int Ww, int mode)
{
    __shared__ float tile[32][33];
    float* dst = mode ? g_lrT : g_featT;
    const int x0 = blockIdx.x * 32;
    const int c0 = blockIdx.y * 32;
    const int bz = blockIdx.z;
    const int b  = bz / Hh, y = bz % Hh;
    const int txi = threadIdx.x, tyi = threadIdx.y;   // 32 x 8
#pragma unroll
    for (int j = 0; j < 4; j++) {
        int c = c0 + tyi + j * 8;
        tile[tyi + j * 8][txi] = src[(((size_t)b * CC + c) * Hh + y) * Ww + x0 + txi];
    }
    __syncthreads();
#pragma unroll
    for (int j = 0; j < 4; j++) {
        int x = x0 + tyi + j * 8;
        dst[(((size_t)b * Hh + y) * Ww + x) * CC + c0 + txi] = tile[txi][tyi + j * 8];
    }
}

// ---------------- kernel 2: weight prep (transpose + bf16 split) ----------------
__global__ void prep_weights(const float* __restrict__ W0, const float* __restrict__ W1,
                             const float* __restrict__ W2, const float* __restrict__ W3)
{
    int id = blockIdx.x * 256 + threadIdx.x;      // 4*256*256
    int l  = id >> 16;
    int n  = (id >> 8) & 255;
    int k  = id & 255;
    const float* Wl = (l == 0) ? W0 : (l == 1) ? W1 : (l == 2) ? W2 : W3;
    // layer0 k remap: k<128 -> feat chan k ; k>=128 -> lr chan => W0 row 130+(k-128)
    int ksrc = (l == 0 && k >= 128) ? (130 + (k - 128)) : k;
    float w = Wl[ksrc * 256 + n];
    __nv_bfloat16 h  = __float2bfloat16(w);
    __nv_bfloat16 lo = __float2bfloat16(w - __bfloat162float(h));
    g_Bh[id] = h;
    g_Bl[id] = lo;
}

// async-stage one k-eighth (32 k = 4 segs) of one layer's B into a 16KB buffer
__device__ __forceinline__ void prefetchB(const __nv_bfloat16* src, uint32_t dbase, int q8, int t)
{
    const uint4* s = (const uint4*)src;
#pragma unroll
    for (int i = 0; i < 8; i++) {
        int idx = i * 128 + t;                    // 0..1023
        int n = idx >> 2, j = idx & 3;
        uint32_t dst = dbase + (uint32_t)((n * 4 + (j ^ ((n >> 1) & 3))) * 16);
        cp16(dst, s + n * 32 + q8 * 4 + j);
    }
}

// split fp32 pair -> bf16 hi/lo, store to A buffers (swizzled)
__device__ __forceinline__ void store_pair(char* smem, int r0, int c, float v0, float v1)
{
    __nv_bfloat16 h0 = __float2bfloat16(v0), h1 = __float2bfloat16(v1);
    __nv_bfloat16 g0 = __float2bfloat16(v0 - __bfloat162float(h0));
    __nv_bfloat16 g1 = __float2bfloat16(v1 - __bfloat162float(h1));
    int unit = r0 * 32 + ((c >> 3) ^ (r0 & 7));
    int boff = unit * 16 + (c & 7) * 2;
    *(uint32_t*)(smem + A_HI + boff) = pk(h0, h1);
    *(uint32_t*)(smem + A_LO + boff) = pk(g0, g1);
}

// ---------------- kernel 3: fused gather + HMMA MLP, 2 CTAs/SM ----------------
__global__ void __launch_bounds__(128, 2) mlp_mma(
    const float* __restrict__ coord, const float* __restrict__ cell,
    const float* __restrict__ W0, const float* __restrict__ b0,
    const float* __restrict__ b1, const float* __restrict__ b2,
    const float* __restrict__ b3,
    const float* __restrict__ W4, const float* __restrict__ b4)
{
    extern __shared__ char smem[];
    float* smf = (float*)smem;
    const int t = threadIdx.x;
    const int lane = t & 31, w = t >> 5;              // 4 warps
    const uint32_t sb = smem_u32(smem);

    // kick off layer-0 stage-0 B prefetch immediately (hidden under gathers)
    prefetchB(g_Bh, sb + BST0, 0, t);
    CP_COMMIT();

    // ---- phase 0: geometry + gathers (2 threads per row, 64 rows) ----
    {
        const int r = t >> 1, half = t & 1;
        const int rg  = blockIdx.x * ROWS + r;
        const int s   = rg >> 17;
        const int rem = rg & (BQ - 1);
        const int b   = rem >> 16;
        const float cy = coord[2 * rem + 0];
        const float cx = coord[2 * rem + 1];
        const float vx = (s & 2) ? 1.f : -1.f;
        const float vy = (s & 1) ? 1.f : -1.f;
        const float r128 = 1.f / 128.f;
        float cy_ = fminf(fmaxf(cy + (vx * r128 + 1e-6f), -1.f + 1e-6f), 1.f - 1e-6f);
        float cx_ = fminf(fmaxf(cx + (vy * r128 + 1e-6f), -1.f + 1e-6f), 1.f - 1e-6f);
        int iy  = min(max((int)floorf(((cy_ + 1.f) * 128.f - 1.f) * 0.5f + 0.5f), 0), 127);
        int ix  = min(max((int)floorf(((cx_ + 1.f) * 128.f - 1.f) * 0.5f + 0.5f), 0), 127);
        int liy = min(max((int)floorf(((cy_ + 1.f) * 64.f - 1.f) * 0.5f + 0.5f), 0), 63);
        int lix = min(max((int)floorf(((cx_ + 1.f) * 64.f - 1.f) * 0.5f + 0.5f), 0), 63);
        if (half == 0) {
            float qy = -1.f + (2.f * (float)iy + 1.f) * r128;
            float qx = -1.f + (2.f * (float)ix + 1.f) * r128;
            float rel_y = (cy - qy) * 128.f;
            float rel_x = (cx - qx) * 128.f;
            smf[XT / 4 + 0 * 64 + r] = rel_y;
            smf[XT / 4 + 1 * 64 + r] = rel_x;
            smf[XT / 4 + 2 * 64 + r] = -1.f + (2.f * (float)liy + 1.f) * (1.f / 64.f);
            smf[XT / 4 + 3 * 64 + r] = -1.f + (2.f * (float)lix + 1.f) * (1.f / 64.f);
            smf[XT / 4 + 4 * 64 + r] = cell[2 * rem + 0] * 128.f;
            smf[XT / 4 + 5 * 64 + r] = cell[2 * rem + 1] * 128.f;
            smf[AREA / 4 + r] = fabsf(rel_y * rel_x) + 1e-9f;
        }
        const float4* fb = half
            ? (const float4*)(g_lrT   + (size_t)(((b * HL + liy) * WL + lix)) * CC)
            : (const float4*)(g_featT + (size_t)(((b * HH + iy) * WW + ix)) * CC);
        const int r7r = r & 7;
#pragma unroll 8
        for (int i = 0; i < 32; i++) {
            float4 u = fb[i];
            int c = half * 128 + i * 4;
            __nv_bfloat16 h0 = __float2bfloat16(u.x), h1 = __float2bfloat16(u.y);
            __nv_bfloat16 h2 = __float2bfloat16(u.z), h3 = __float2bfloat16(u.w);
            __nv_bfloat16 l0 = __float2bfloat16(u.x - __bfloat162float(h0));
            __nv_bfloat16 l1 = __float2bfloat16(u.y - __bfloat162float(h1));
            __nv_bfloat16 l2 = __float2bfloat16(u.z - __bfloat162float(h2));
            __nv_bfloat16 l3 = __float2bfloat16(u.w - __bfloat162float(h3));
            int unit = r * 32 + ((c >> 3) ^ r7r);
            int boff = unit * 16 + (c & 7) * 2;
            *(uint2*)(smem + A_HI + boff) = make_uint2(pk(h0, h1), pk(h2, h3));
            *(uint2*)(smem + A_LO + boff) = make_uint2(pk(l0, l1), pk(l2, l3));
        }
        // wtail: W0 rows {128,129,258,259,260,261}
        {
            const int tailrow[6] = {128, 129, 258, 259, 260, 261};
            for (int idx = t; idx < 1536; idx += 128) {
                int jj = idx >> 8, c = idx & 255;
                smf[WT / 4 + jj * 256 + c] = W0[tailrow[jj] * 256 + c];
            }
            for (int idx = t; idx < 768; idx += 128)
                smf[W4S / 4 + idx] = W4[(idx & 255) * 3 + (idx >> 8)];
        }
    }

    // ---- ldmatrix lane geometry ----
    const int laneAr = lane & 15, sa = lane >> 4, la7 = lane & 7;
    const int nb0 = w * 64 + ((lane >> 4) << 3) + (lane & 7);   // warp owns 64 n-cols
    const int sbB = (lane >> 3) & 1;
    const int rq = lane >> 2, cq = (lane & 3) * 2;

    float acc[4][32];

    for (int l = 0; l < 4; l++) {
        __syncthreads();          // prev epilogue done (BIAS/A safe to rewrite)
        {
            const float* bg = (l == 0) ? b0 : (l == 1) ? b1 : (l == 2) ? b2 : b3;
            smf[BIAS / 4 + t] = bg[t];
            smf[BIAS / 4 + 128 + t] = bg[128 + t];
        }
#pragma unroll
        for (int mt = 0; mt < 4; mt++)
#pragma unroll
            for (int q = 0; q < 32; q++) acc[mt][q] = 0.f;

        // 16 stages: s = 2*q8 + sel, sel 0 = W-hi (A_HI + A_LO terms), 1 = W-lo (A_HI)
#pragma unroll 1
        for (int s = 0; s < 16; s++) {
            CP_WAIT0();
            __syncthreads();              // stage s data visible; prev stage MMA done
            if (s < 15) {                 // prefetch next stage into other buffer
                int ns = s + 1;
                const __nv_bfloat16* nsrc = ((ns & 1) ? g_Bl : g_Bh) + ((size_t)l << 16);
                prefetchB(nsrc, sb + ((ns & 1) ? BST1 : BST0), ns >> 1, t);
                CP_COMMIT();
            }
            const uint32_t Bb = sb + ((s & 1) ? BST1 : BST0);
            const int q8 = s >> 1;
            const bool hiStage = ((s & 1) == 0);
#pragma unroll
            for (int ks = 0; ks < 2; ks++) {
                uint32_t bq[8][2];
                {
                    int seg = ks * 2 + sbB;
#pragma unroll
                    for (int g = 0; g < 4; g++) {
                        int n0 = nb0 + 16 * g;
                        uint32_t ad = Bb + (uint32_t)((n0 * 4 + (seg ^ ((n0 >> 1) & 3))) * 16);
                        ldsm4(bq[2 * g][0], bq[2 * g][1], bq[2 * g + 1][0], bq[2 * g + 1][1], ad);
                    }
                }
                int segA = (q8 * 4 + ks * 2 + sa) ^ la7;
#pragma unroll
                for (int mt = 0; mt < 4; mt++) {
                    int rowA = mt * 16 + laneAr;
                    uint32_t aq[4];
                    ldsm4(aq[0], aq[1], aq[2], aq[3],
                          sb + A_HI + (uint32_t)((rowA * 32 + segA) * 16));
#pragma unroll
                    for (int j = 0; j < 8; j++) mma_bf16(acc[mt] + 4 * j, aq, bq[j]);
                    if (hiStage) {        // A_LO x W_hi correction term
                        ldsm4(aq[0], aq[1], aq[2], aq[3],
                              sb + A_LO + (uint32_t)((rowA * 32 + segA) * 16));
#pragma unroll
                        for (int j = 0; j < 8; j++) mma_bf16(acc[mt] + 4 * j, aq, bq[j]);
                    }
                }
            }
        }
        if (l < 3) {                      // prefetch next layer stage 0 (under epilogue)
            prefetchB(g_Bh + ((size_t)(l + 1) << 16), sb + BST0, 0, t);
            CP_COMMIT();
        }
        __syncthreads();                  // all MMA done; safe to overwrite A / v-buffer

        // ---- epilogue ----
#pragma unroll
        for (int mt = 0; mt < 4; mt++) {
            int r0 = mt * 16 + rq;
            float xtr[6], xtr8[6];
            if (l == 0) {
#pragma unroll
                for (int jj = 0; jj < 6; jj++) {
                    xtr[jj]  = smf[XT / 4 + jj * 64 + r0];
                    xtr8[jj] = smf[XT / 4 + jj * 64 + r0 + 8];
                }
            }
#pragma unroll
            for (int j = 0; j < 8; j++) {
                int c = w * 64 + j * 8 + cq;
                float bs0 = smf[BIAS / 4 + c], bs1 = smf[BIAS / 4 + c + 1];
                float v0 = acc[mt][4 * j + 0] + bs0;
                float v1 = acc[mt][4 * j + 1] + bs1;
                float v2 = acc[mt][4 * j + 2] + bs0;
                float v3 = acc[mt][4 * j + 3] + bs1;
                if (l == 0) {
#pragma unroll
                    for (int jj = 0; jj < 6; jj++) {
                        float w0v = smf[WT / 4 + jj * 256 + c];
                        float w1v = smf[WT / 4 + jj * 256 + c + 1];
                        v0 = fmaf(xtr[jj],  w0v, v0);
                        v1 = fmaf(xtr[jj],  w1v, v1);
                        v2 = fmaf(xtr8[jj], w0v, v2);
                        v3 = fmaf(xtr8[jj], w1v, v3);
                    }
                }
                v0 = fmaxf(v0, 0.f); v1 = fmaxf(v1, 0.f);
                v2 = fmaxf(v2, 0.f); v3 = fmaxf(v3, 0.f);
                if (l < 3) {
                    store_pair(smem, r0,     c, v0, v1);
                    store_pair(smem, r0 + 8, c, v2, v3);
                } else {
                    *(float2*)(smf + r0 * VSTR + c)       = make_float2(v0, v1);
                    *(float2*)(smf + (r0 + 8) * VSTR + c) = make_float2(v2, v3);
                }
            }
        }
    }

    // ---- head: out = v @ W4 + b4 ----
    __syncthreads();
    {
        const int hr = t >> 1, hh = t & 1;            // 64 rows x 2 halves
        float a0 = 0.f, a1 = 0.f, a2 = 0.f;
        const float* vrow = smf + hr * VSTR + hh * 128;
        const float* w4p  = smf + W4S / 4 + hh * 128;
#pragma unroll 8
        for (int c2 = 0; c2 < 128; c2++) {
            float x = vrow[c2];
            a0 = fmaf(x, w4p[0 * 256 + c2], a0);
            a1 = fmaf(x, w4p[1 * 256 + c2], a1);
            a2 = fmaf(x, w4p[2 * 256 + c2], a2);
        }
        __syncthreads();          // v-buffer reads done before XT overwrite
        smf[XT / 4 + t * 3 + 0] = a0;
        smf[XT / 4 + t * 3 + 1] = a1;
        smf[XT / 4 + t * 3 + 2] = a2;
    }
    __syncthreads();
    if (t < 64) {
        const size_t rgi = (size_t)(blockIdx.x * ROWS + t) * 4;
        g_predArea[rgi + 0] = smf[XT / 4 + (2 * t) * 3 + 0] + smf[XT / 4 + (2 * t + 1) * 3 + 0] + b4[0];
        g_predArea[rgi + 1] = smf[XT / 4 + (2 * t) * 3 + 1] + smf[XT / 4 + (2 * t + 1) * 3 + 1] + b4[1];
        g_predArea[rgi + 2] = smf[XT / 4 + (2 * t) * 3 + 2] + smf[XT / 4 + (2 * t + 1) * 3 + 2] + b4[2];
        g_predArea[rgi + 3] = smf[AREA / 4 + t];
    }
}

// ---------------- kernel 4: local-ensemble combine (diagonal area swap) -------------
__global__ void combine_kernel(float* __restrict__ out)
{
    const int idx = blockIdx.x * 256 + threadIdx.x;     // b*Q + q
    const float4 p0 = *(const float4*)(g_predArea + ((size_t)(0 * BQ + idx)) * 4);
    const float4 p1 = *(const float4*)(g_predArea + ((size_t)(1 * BQ + idx)) * 4);
    const float4 p2 = *(const float4*)(g_predArea + ((size_t)(2 * BQ + idx)) * 4);
    const float4 p3 = *(const float4*)(g_predArea + ((size_t)(3 * BQ + idx)) * 4);
    const float tot = p0.w + p1.w + p2.w + p3.w;
    const float w0 = p3.w / tot, w1 = p2.w / tot, w2 = p1.w / tot, w3 = p0.w / tot;
    out[idx * 3 + 0] = p0.x * w0 + p1.x * w1 + p2.x * w2 + p3.x * w3;
    out[idx * 3 + 1] = p0.y * w0 + p1.y * w1 + p2.y * w2 + p3.y * w3;
    out[idx * 3 + 2] = p0.z * w0 + p1.z * w1 + p2.z * w2 + p3.z * w3;
}

// ---------------- launch ----------------
extern "C" void kernel_launch(void* const* d_in, const int* in_sizes, int n_in,
                              void* d_out, int out_size)
{
    const float* feat  = (const float*)d_in[0];
    const float* lrft  = (const float*)d_in[1];
    const float* coord = (const float*)d_in[2];
    const float* cell  = (const float*)d_in[3];
    const float* W0 = (const float*)d_in[4];   const float* b0 = (const float*)d_in[5];
    const float* W1 = (const float*)d_in[6];   const float* b1 = (const float*)d_in[7];
    const float* W2 = (const float*)d_in[8];   const float* b2 = (const float*)d_in[9];
    const float* W3 = (const float*)d_in[10];  const float* b3 = (const float*)d_in[11];
    const float* W4 = (const float*)d_in[12];  const float* b4 = (const float*)d_in[13];
    float* out = (float*)d_out;

    cudaFuncSetAttribute((const void*)mlp_mma,
                         cudaFuncAttributeMaxDynamicSharedMemorySize, SMEMB);

    dim3 blkT(32, 8);
    transpose_kernel<<<dim3(WW / 32, CC / 32, BB * HH), blkT>>>(feat, HH, WW, 0);
    transpose_kernel<<<dim3(WL / 32, CC / 32, BB * HL), blkT>>>(lrft, HL, WL, 1);
    prep_weights<<<1024, 256>>>(W0, W1, W2, W3);

    mlp_mma<<<NCTA, 128, SMEMB>>>(coord, cell, W0, b0, b1, b2, b3, W4, b4);

    combine_kernel<<<BQ / 256, 256>>>(out);
}

// round 15
// speedup vs baseline: 1.1680x; 1.0984x over previous
#include <cuda_runtime.h>
#include <cuda_bf16.h>
#include <cstdint>

// ---------------- problem constants ----------------
#define BB   2
#define CC   128
#define HH   128
#define WW   128
#define HL   64
#define WL   64
#define QQ   65536
#define BQ   (BB*QQ)          // 131072
#define RTOT (4*BQ)           // 524288
#define ROWS 128              // rows per CTA (MMA M)
#define NCTA (RTOT/ROWS)      // 4096

// ---------------- smem layout (bytes) ----------------
// A buffers: [128 r][32 segs of 8 bf16], unit = r*32 + (seg ^ (r&7)), 16B units
#define A_HI 0                // 65536
#define A_LO 65536            // 65536
// B staging: 4 x 16KB k-eighth buffers [256 n][4 segs], unit = n*4 + (sg ^ ((n>>1)&3))
#define BH0  131072           // 16384
#define BL0  147456           // 16384
#define BH1  163840           // 16384
#define BL1  180224           // 16384
#define BIAS 196608           // 256 f32
#define W4S  197632           // [3][256] f32
#define WT   200704           // wtail [6][256] f32
#define XT   206848           // xtail [6][128] f32 (reused for head partials)
#define AREA 209920           // 128 f32
#define SMEMB 210432
#define VSTR 258              // fp32 v-buffer row stride (overlays A_HI/A_LO/BH0 at l==3)

// ---------------- device scratch (static; no allocation) ----------------
__device__ float g_featT[(size_t)BB*HH*WW*CC];       // NHWC feat fp32
__device__ float g_lrT  [(size_t)BB*HL*WL*CC];       // NHWC lr fp32
__device__ float g_predArea[(size_t)RTOT*4];         // pred.xyz + area
// weights pre-transposed to [layer][n 0..255][k 0..255] bf16 (hi and residual-lo)
__device__ __nv_bfloat16 g_Bh[4*65536];
__device__ __nv_bfloat16 g_Bl[4*65536];

__device__ __forceinline__ uint32_t smem_u32(const void* p) {
    uint32_t a;
    asm("{ .reg .u64 t; cvta.to.shared.u64 t, %1; cvt.u32.u64 %0, t; }" : "=r"(a) : "l"(p));
    return a;
}
__device__ __forceinline__ void ldsm4(uint32_t& q0, uint32_t& q1, uint32_t& q2, uint32_t& q3,
                                      uint32_t addr) {
    asm volatile("ldmatrix.sync.aligned.m8n8.x4.shared.b16 {%0,%1,%2,%3}, [%4];"
                 : "=r"(q0), "=r"(q1), "=r"(q2), "=r"(q3) : "r"(addr));
}
__device__ __forceinline__ void mma_bf16(float* d, const uint32_t* a, const uint32_t* b) {
    asm volatile("mma.sync.aligned.m16n8k16.row.col.f32.bf16.bf16.f32 "
                 "{%0,%1,%2,%3}, {%4,%5,%6,%7}, {%8,%9}, {%0,%1,%2,%3};"
                 : "+f"(d[0]), "+f"(d[1]), "+f"(d[2]), "+f"(d[3])
                 : "r"(a[0]), "r"(a[1]), "r"(a[2]), "r"(a[3]), "r"(b[0]), "r"(b[1]));
}
__device__ __forceinline__ uint32_t pk(__nv_bfloat16 a, __nv_bfloat16 b) {
    return (uint32_t)__bfloat16_as_ushort(a) | ((uint32_t)__bfloat16_as_ushort(b) << 16);
}
__device__ __forceinline__ void cp16(uint32_t dst, const void* src) {
    asm volatile("cp.async.cg.shared.global [%0], [%1], 16;" :: "r"(dst), "l"(src));
}
#define CP_COMMIT() asm volatile("cp.async.commit_group;" ::: "memory")
#define CP_WAIT0()  asm volatile("cp.async.wait_group 0;" ::: "memory")

// ---------------- kernel 1: NCHW -> NHWC tiled transpose ----------------
__global__ void transpose_kernel(const float* __restrict__ src, int Hh, int Ww, int mode)
{
    __shared__ float tile[32][33];
    float* dst = mode ? g_lrT : g_featT;
    const int x0 = blockIdx.x * 32;
    const int c0 = blockIdx.y * 32;
    const int bz = blockIdx.z;
    const int b  = bz / Hh, y = bz % Hh;
    const int txi = threadIdx.x, tyi = threadIdx.y;   // 32 x 8
#pragma unroll
    for (int j = 0; j < 4; j++) {
        int c = c0 + tyi + j * 8;
        tile[tyi + j * 8][txi] = src[(((size_t)b * CC + c) * Hh + y) * Ww + x0 + txi];
    }
    __syncthreads();
#pragma unroll
    for (int j = 0; j < 4; j++) {
        int x = x0 + tyi + j * 8;
        dst[(((size_t)b * Hh + y) * Ww + x) * CC + c0 + txi] = tile[txi][tyi + j * 8];
    }
}

// ---------------- kernel 2: weight prep (transpose + bf16 split) ----------------
__global__ void prep_weights(const float* __restrict__ W0, const float* __restrict__ W1,
                             const float* __restrict__ W2, const float* __restrict__ W3)
{
    int id = blockIdx.x * 256 + threadIdx.x;      // 4*256*256
    int l  = id >> 16;
    int n  = (id >> 8) & 255;
    int k  = id & 255;
    const float* Wl = (l == 0) ? W0 : (l == 1) ? W1 : (l == 2) ? W2 : W3;
    // layer0 k remap: k<128 -> feat chan k ; k>=128 -> lr chan => W0 row 130+(k-128)
    int ksrc = (l == 0 && k >= 128) ? (130 + (k - 128)) : k;
    float w = Wl[ksrc * 256 + n];
    __nv_bfloat16 h  = __float2bfloat16(w);
    __nv_bfloat16 lo = __float2bfloat16(w - __bfloat162float(h));
    g_Bh[id] = h;
    g_Bl[id] = lo;
}

// async-stage one k-eighth (32 k = 4 segs) of one layer's B into a 16KB buffer
__device__ __forceinline__ void prefetch8(const __nv_bfloat16* src, uint32_t dbase, int q8, int t)
{
    const uint4* s = (const uint4*)src;
#pragma unroll
    for (int i = 0; i < 4; i++) {
        int idx = i * 256 + t;                    // 0..1023
        int n = idx >> 2, j = idx & 3;
        uint32_t dst = dbase + (uint32_t)((n * 4 + (j ^ ((n >> 1) & 3))) * 16);
        cp16(dst, s + n * 32 + q8 * 4 + j);
    }
}

// split fp32 pair -> bf16 hi/lo, store to A buffers (swizzled)
__device__ __forceinline__ void store_pair(char* smem, int r0, int c, float v0, float v1)
{
    __nv_bfloat16 h0 = __float2bfloat16(v0), h1 = __float2bfloat16(v1);
    __nv_bfloat16 g0 = __float2bfloat16(v0 - __bfloat162float(h0));
    __nv_bfloat16 g1 = __float2bfloat16(v1 - __bfloat162float(h1));
    int unit = r0 * 32 + ((c >> 3) ^ (r0 & 7));
    int boff = unit * 16 + (c & 7) * 2;
    *(uint32_t*)(smem + A_HI + boff) = pk(h0, h1);
    *(uint32_t*)(smem + A_LO + boff) = pk(g0, g1);
}

// ---------------- kernel 3: fused gather + HMMA MLP, merged-term chunks ------------
__global__ void __launch_bounds__(256, 1) mlp_mma(
    const float* __restrict__ coord, const float* __restrict__ cell,
    const float* __restrict__ W0, const float* __restrict__ b0,
    const float* __restrict__ b1, const float* __restrict__ b2,
    const float* __restrict__ b3,
    const float* __restrict__ W4, const float* __restrict__ b4)
{
    extern __shared__ char smem[];
    float* smf = (float*)smem;
    const int t = threadIdx.x;
    const int lane = t & 31, w = t >> 5;
    const uint32_t sb = smem_u32(smem);

    // kick off layer-0 chunk-0 (Bh + Bl eighth) prefetch, hidden under gathers
    prefetch8(g_Bh, sb + BH0, 0, t);
    prefetch8(g_Bl, sb + BL0, 0, t);
    CP_COMMIT();

    // ---- phase 0: geometry + gathers (2 threads per row) ----
    {
        const int r = t >> 1, half = t & 1;
        const int rg  = blockIdx.x * ROWS + r;
        const int s   = rg >> 17;
        const int rem = rg & (BQ - 1);
        const int b   = rem >> 16;
        const float cy = coord[2 * rem + 0];
        const float cx = coord[2 * rem + 1];
        const float vx = (s & 2) ? 1.f : -1.f;
        const float vy = (s & 1) ? 1.f : -1.f;
        const float r128 = 1.f / 128.f;
        float cy_ = fminf(fmaxf(cy + (vx * r128 + 1e-6f), -1.f + 1e-6f), 1.f - 1e-6f);
        float cx_ = fminf(fmaxf(cx + (vy * r128 + 1e-6f), -1.f + 1e-6f), 1.f - 1e-6f);
        int iy  = min(max((int)floorf(((cy_ + 1.f) * 128.f - 1.f) * 0.5f + 0.5f), 0), 127);
        int ix  = min(max((int)floorf(((cx_ + 1.f) * 128.f - 1.f) * 0.5f + 0.5f), 0), 127);
        int liy = min(max((int)floorf(((cy_ + 1.f) * 64.f - 1.f) * 0.5f + 0.5f), 0), 63);
        int lix = min(max((int)floorf(((cx_ + 1.f) * 64.f - 1.f) * 0.5f + 0.5f), 0), 63);
        if (half == 0) {
            float qy = -1.f + (2.f * (float)iy + 1.f) * r128;
            float qx = -1.f + (2.f * (float)ix + 1.f) * r128;
            float rel_y = (cy - qy) * 128.f;
            float rel_x = (cx - qx) * 128.f;
            smf[XT / 4 + 0 * 128 + r] = rel_y;
            smf[XT / 4 + 1 * 128 + r] = rel_x;
            smf[XT / 4 + 2 * 128 + r] = -1.f + (2.f * (float)liy + 1.f) * (1.f / 64.f);
            smf[XT / 4 + 3 * 128 + r] = -1.f + (2.f * (float)lix + 1.f) * (1.f / 64.f);
            smf[XT / 4 + 4 * 128 + r] = cell[2 * rem + 0] * 128.f;
            smf[XT / 4 + 5 * 128 + r] = cell[2 * rem + 1] * 128.f;
            smf[AREA / 4 + r] = fabsf(rel_y * rel_x) + 1e-9f;
        }
        const float4* fb = half
            ? (const float4*)(g_lrT   + (size_t)(((b * HL + liy) * WL + lix)) * CC)
            : (const float4*)(g_featT + (size_t)(((b * HH + iy) * WW + ix)) * CC);
        const int r7r = r & 7;
#pragma unroll 8
        for (int i = 0; i < 32; i++) {
            float4 u = fb[i];
            int c = half * 128 + i * 4;
            __nv_bfloat16 h0 = __float2bfloat16(u.x), h1 = __float2bfloat16(u.y);
            __nv_bfloat16 h2 = __float2bfloat16(u.z), h3 = __float2bfloat16(u.w);
            __nv_bfloat16 l0 = __float2bfloat16(u.x - __bfloat162float(h0));
            __nv_bfloat16 l1 = __float2bfloat16(u.y - __bfloat162float(h1));
            __nv_bfloat16 l2 = __float2bfloat16(u.z - __bfloat162float(h2));
            __nv_bfloat16 l3 = __float2bfloat16(u.w - __bfloat162float(h3));
            int unit = r * 32 + ((c >> 3) ^ r7r);
            int boff = unit * 16 + (c & 7) * 2;
            *(uint2*)(smem + A_HI + boff) = make_uint2(pk(h0, h1), pk(h2, h3));
            *(uint2*)(smem + A_LO + boff) = make_uint2(pk(l0, l1), pk(l2, l3));
        }
        // wtail: W0 rows {128,129,258,259,260,261}
        {
            const int tailrow[6] = {128, 129, 258, 259, 260, 261};
            for (int idx = t; idx < 1536; idx += 256) {
                int jj = idx >> 8, c = idx & 255;
                smf[WT / 4 + jj * 256 + c] = W0[tailrow[jj] * 256 + c];
            }
            for (int idx = t; idx < 768; idx += 256)
                smf[W4S / 4 + idx] = W4[(idx & 255) * 3 + (idx >> 8)];
        }
    }

    // ---- ldmatrix lane geometry ----
    const int laneAr = lane & 15, sa = lane >> 4, la7 = lane & 7;
    const int nb0 = w * 32 + ((lane >> 4) << 3) + (lane & 7);
    const int sbB = (lane >> 3) & 1;
    const int rq = lane >> 2, cq = (lane & 3) * 2;

    float acc[8][16];

    for (int l = 0; l < 4; l++) {
        __syncthreads();          // prev epilogue done (BIAS/A safe to rewrite)
        {
            const float* bg = (l == 0) ? b0 : (l == 1) ? b1 : (l == 2) ? b2 : b3;
            smf[BIAS / 4 + t] = bg[t];
        }
#pragma unroll
        for (int mt = 0; mt < 8; mt++)
#pragma unroll
            for (int q = 0; q < 16; q++) acc[mt][q] = 0.f;

        // 8 chunks (k-eighths); each chunk holds Bh AND Bl, all 3 terms computed
#pragma unroll 1
        for (int c = 0; c < 8; c++) {
            CP_WAIT0();
            __syncthreads();              // chunk c data visible; prev chunk MMA done
            if (c < 7) {                  // prefetch next chunk into other pair
                int nc = c + 1;
                uint32_t bh = sb + ((nc & 1) ? BH1 : BH0);
                uint32_t bl = sb + ((nc & 1) ? BL1 : BL0);
                prefetch8(g_Bh + ((size_t)l << 16), bh, nc, t);
                prefetch8(g_Bl + ((size_t)l << 16), bl, nc, t);
                CP_COMMIT();
            }
            const uint32_t BbH = sb + ((c & 1) ? BH1 : BH0);
            const uint32_t BbL = sb + ((c & 1) ? BL1 : BL0);
#pragma unroll
            for (int ks = 0; ks < 2; ks++) {
                uint32_t bh[4][2], bl[4][2];
                {
                    int seg = ks * 2 + sbB;
                    int n0 = nb0, n1 = nb0 + 16;
                    uint32_t u0 = (uint32_t)((n0 * 4 + (seg ^ ((n0 >> 1) & 3))) * 16);
                    uint32_t u1 = (uint32_t)((n1 * 4 + (seg ^ ((n1 >> 1) & 3))) * 16);
                    ldsm4(bh[0][0], bh[0][1], bh[1][0], bh[1][1], BbH + u0);
                    ldsm4(bh[2][0], bh[2][1], bh[3][0], bh[3][1], BbH + u1);
                    ldsm4(bl[0][0], bl[0][1], bl[1][0], bl[1][1], BbL + u0);
                    ldsm4(bl[2][0], bl[2][1], bl[3][0], bl[3][1], BbL + u1);
                }
                int segA = (c * 4 + ks * 2 + sa) ^ la7;
#pragma unroll
                for (int mt = 0; mt < 8; mt++) {
                    int rowA = mt * 16 + laneAr;
                    uint32_t aq[4];
                    ldsm4(aq[0], aq[1], aq[2], aq[3],
                          sb + A_HI + (uint32_t)((rowA * 32 + segA) * 16));
#pragma unroll
                    for (int j = 0; j < 4; j++) mma_bf16(acc[mt] + 4 * j, aq, bh[j]);
#pragma unroll
                    for (int j = 0; j < 4; j++) mma_bf16(acc[mt] + 4 * j, aq, bl[j]);
                    ldsm4(aq[0], aq[1], aq[2], aq[3],
                          sb + A_LO + (uint32_t)((rowA * 32 + segA) * 16));
#pragma unroll
                    for (int j = 0; j < 4; j++) mma_bf16(acc[mt] + 4 * j, aq, bh[j]);
                }
            }
        }
        if (l < 3) {                      // prefetch next layer chunk 0 (under epilogue)
            prefetch8(g_Bh + ((size_t)(l + 1) << 16), sb + BH0, 0, t);
            prefetch8(g_Bl + ((size_t)(l + 1) << 16), sb + BL0, 0, t);
            CP_COMMIT();
        }
        __syncthreads();                  // all MMA done; safe to overwrite A / v-buffer

        // ---- epilogue ----
        float wtc[6][8];
        if (l == 0) {
#pragma unroll
            for (int jj = 0; jj < 6; jj++)
#pragma unroll
                for (int j = 0; j < 4; j++) {
                    int c = w * 32 + j * 8 + cq;
                    wtc[jj][2 * j]     = smf[WT / 4 + jj * 256 + c];
                    wtc[jj][2 * j + 1] = smf[WT / 4 + jj * 256 + c + 1];
                }
        }
#pragma unroll
        for (int mt = 0; mt < 8; mt++) {
            int r0 = mt * 16 + rq;
            float xtr[6], xtr8[6];
            if (l == 0) {
#pragma unroll
                for (int jj = 0; jj < 6; jj++) {
                    xtr[jj]  = smf[XT / 4 + jj * 128 + r0];
                    xtr8[jj] = smf[XT / 4 + jj * 128 + r0 + 8];
                }
            }
#pragma unroll
            for (int j = 0; j < 4; j++) {
                int c = w * 32 + j * 8 + cq;
                float bs0 = smf[BIAS / 4 + c], bs1 = smf[BIAS / 4 + c + 1];
                float v0 = acc[mt][4 * j + 0] + bs0;
                float v1 = acc[mt][4 * j + 1] + bs1;
                float v2 = acc[mt][4 * j + 2] + bs0;
                float v3 = acc[mt][4 * j + 3] + bs1;
                if (l == 0) {
#pragma unroll
                    for (int jj = 0; jj < 6; jj++) {
                        v0 = fmaf(xtr[jj],  wtc[jj][2 * j],     v0);
                        v1 = fmaf(xtr[jj],  wtc[jj][2 * j + 1], v1);
                        v2 = fmaf(xtr8[jj], wtc[jj][2 * j],     v2);
                        v3 = fmaf(xtr8[jj], wtc[jj][2 * j + 1], v3);
                    }
                }
                v0 = fmaxf(v0, 0.f); v1 = fmaxf(v1, 0.f);
                v2 = fmaxf(v2, 0.f); v3 = fmaxf(v3, 0.f);
                if (l < 3) {
                    store_pair(smem, r0,     c, v0, v1);
                    store_pair(smem, r0 + 8, c, v2, v3);
                } else {
                    *(float2*)(smf + r0 * VSTR + c)       = make_float2(v0, v1);
                    *(float2*)(smf + (r0 + 8) * VSTR + c) = make_float2(v2, v3);
                }
            }
        }
    }

    // ---- head: out = v @ W4 + b4 ----
    __syncthreads();
    {
        const int hr = t >> 1, hh = t & 1;
        float a0 = 0.f, a1 = 0.f, a2 = 0.f;
        const float* vrow = smf + hr * VSTR + hh * 128;
        const float* w4p  = smf + W4S / 4 + hh * 128;
#pragma unroll 8
        for (int c2 = 0; c2 < 128; c2++) {
            float x = vrow[c2];
            a0 = fmaf(x, w4p[0 * 256 + c2], a0);
            a1 = fmaf(x, w4p[1 * 256 + c2], a1);
            a2 = fmaf(x, w4p[2 * 256 + c2], a2);
        }
        __syncthreads();          // v-buffer reads done before XT overwrite
        smf[XT / 4 + t * 3 + 0] = a0;
        smf[XT / 4 + t * 3 + 1] = a1;
        smf[XT / 4 + t * 3 + 2] = a2;
    }
    __syncthreads();
    if (t < 128) {
        const size_t rgi = (size_t)(blockIdx.x * ROWS + t) * 4;
        g_predArea[rgi + 0] = smf[XT / 4 + (2 * t) * 3 + 0] + smf[XT / 4 + (2 * t + 1) * 3 + 0] + b4[0];
        g_predArea[rgi + 1] = smf[XT / 4 + (2 * t) * 3 + 1] + smf[XT / 4 + (2 * t + 1) * 3 + 1] + b4[1];
        g_predArea[rgi + 2] = smf[XT / 4 + (2 * t) * 3 + 2] + smf[XT / 4 + (2 * t + 1) * 3 + 2] + b4[2];
        g_predArea[rgi + 3] = smf[AREA / 4 + t];
    }
}

// ---------------- kernel 4: local-ensemble combine (diagonal area swap) -------------
__global__ void combine_kernel(float* __restrict__ out)
{
    const int idx = blockIdx.x * 256 + threadIdx.x;     // b*Q + q
    const float4 p0 = *(const float4*)(g_predArea + ((size_t)(0 * BQ + idx)) * 4);
    const float4 p1 = *(const float4*)(g_predArea + ((size_t)(1 * BQ + idx)) * 4);
    const float4 p2 = *(const float4*)(g_predArea + ((size_t)(2 * BQ + idx)) * 4);
    const float4 p3 = *(const float4*)(g_predArea + ((size_t)(3 * BQ + idx)) * 4);
    const float tot = p0.w + p1.w + p2.w + p3.w;
    const float w0 = p3.w / tot, w1 = p2.w / tot, w2 = p1.w / tot, w3 = p0.w / tot;
    out[idx * 3 + 0] = p0.x * w0 + p1.x * w1 + p2.x * w2 + p3.x * w3;
    out[idx * 3 + 1] = p0.y * w0 + p1.y * w1 + p2.y * w2 + p3.y * w3;
    out[idx * 3 + 2] = p0.z * w0 + p1.z * w1 + p2.z * w2 + p3.z * w3;
}

// ---------------- launch ----------------
extern "C" void kernel_launch(void* const* d_in, const int* in_sizes, int n_in,
                              void* d_out, int out_size)
{
    const float* feat  = (const float*)d_in[0];
    const float* lrft  = (const float*)d_in[1];
    const float* coord = (const float*)d_in[2];
    const float* cell  = (const float*)d_in[3];
    const float* W0 = (const float*)d_in[4];   const float* b0 = (const float*)d_in[5];
    const float* W1 = (const float*)d_in[6];   const float* b1 = (const float*)d_in[7];
    const float* W2 = (const float*)d_in[8];   const float* b2 = (const float*)d_in[9];
    const float* W3 = (const float*)d_in[10];  const float* b3 = (const float*)d_in[11];
    const float* W4 = (const float*)d_in[12];  const float* b4 = (const float*)d_in[13];
    float* out = (float*)d_out;

    cudaFuncSetAttribute((const void*)mlp_mma,
                         cudaFuncAttributeMaxDynamicSharedMemorySize, SMEMB);

    dim3 blkT(32, 8);
    transpose_kernel<<<dim3(WW / 32, CC / 32, BB * HH), blkT>>>(feat, HH, WW, 0);
    transpose_kernel<<<dim3(WL / 32, CC / 32, BB * HL), blkT>>>(lrft, HL, WL, 1);
    prep_weights<<<1024, 256>>>(W0, W1, W2, W3);

    mlp_mma<<<NCTA, 256, SMEMB>>>(coord, cell, W0, b0, b1, b2, b3, W4, b4);

    combine_kernel<<<BQ / 256, 256>>>(out);
}